// round 15
// baseline (speedup 1.0000x reference)
#include <cuda_runtime.h>
#include <cuda_bf16.h>
#include <cstdint>

#define BB 2
#define SS 2048
#define EE 1024
#define HH 16
#define DD 64
#define BS (BB*SS)      // 4096
#define BHS (BB*HH*SS)  // 65536

// ---------------------------------------------------------------------------
// Scratch (device globals; no allocation allowed)
// ---------------------------------------------------------------------------
__device__ float g_l[BHS];           // softmax row sums

__device__ __nv_bfloat16 g_qh[BS*EE], g_ql[BS*EE];
__device__ __nv_bfloat16 g_kh[BS*EE], g_kl[BS*EE];
__device__ __nv_bfloat16 g_vh[BS*EE], g_vl[BS*EE];
__device__ __nv_bfloat16 g_wth[BS*EE], g_wtl[BS*EE];
__device__ __nv_bfloat16 g_WqhT[EE*EE], g_WqlT[EE*EE];
__device__ __nv_bfloat16 g_WkhT[EE*EE], g_WklT[EE*EE];
__device__ __nv_bfloat16 g_WvhT[EE*EE], g_WvlT[EE*EE];
__device__ __nv_bfloat16 g_WohT[EE*EE], g_WolT[EE*EE];
__device__ __nv_bfloat16 g_PQh[BHS*DD], g_PQl[BHS*DD];
__device__ __nv_bfloat16 g_PKh[BHS*DD], g_PKl[BHS*DD];
__device__ __nv_bfloat16 g_PVth[BHS*DD], g_PVtl[BHS*DD];

// ---------------------------------------------------------------------------
// PTX helpers
// ---------------------------------------------------------------------------
__device__ __forceinline__ void mma16816(float* c, const uint32_t* a, const uint32_t* b) {
    asm volatile(
        "mma.sync.aligned.m16n8k16.row.col.f32.bf16.bf16.f32 "
        "{%0,%1,%2,%3}, {%4,%5,%6,%7}, {%8,%9}, {%0,%1,%2,%3};"
        : "+f"(c[0]), "+f"(c[1]), "+f"(c[2]), "+f"(c[3])
        : "r"(a[0]), "r"(a[1]), "r"(a[2]), "r"(a[3]), "r"(b[0]), "r"(b[1]));
}

__device__ __forceinline__ void ldm4(uint32_t* r, uint32_t saddr) {
    asm volatile("ldmatrix.sync.aligned.m8n8.x4.shared.b16 {%0,%1,%2,%3}, [%4];"
                 : "=r"(r[0]), "=r"(r[1]), "=r"(r[2]), "=r"(r[3]) : "r"(saddr));
}

__device__ __forceinline__ uint32_t smem_u32(const void* p) {
    uint32_t a;
    asm("{ .reg .u64 t; cvta.to.shared.u64 t, %1; cvt.u32.u64 %0, t; }" : "=r"(a) : "l"(p));
    return a;
}

#define CP_ASYNC16(dst, src) \
    asm volatile("cp.async.cg.shared.global [%0], [%1], 16;" :: "r"(dst), "l"(src))
#define CP_COMMIT() asm volatile("cp.async.commit_group;" ::: "memory")
#define CP_WAIT(n)  asm volatile("cp.async.wait_group %0;" :: "n"(n) : "memory")

__device__ __forceinline__ __nv_bfloat162 split_hi2(float x, float y) {
    return __nv_bfloat162(__float2bfloat16_rn(x), __float2bfloat16_rn(y));
}
__device__ __forceinline__ __nv_bfloat162 split_lo2(float x, float y,
                                                    __nv_bfloat162 h) {
    return __nv_bfloat162(__float2bfloat16_rn(x - __bfloat162float(h.x)),
                          __float2bfloat16_rn(y - __bfloat162float(h.y)));
}
__device__ __forceinline__ uint32_t b2u(__nv_bfloat162 v) {
    return *reinterpret_cast<uint32_t*>(&v);
}

// ---------------------------------------------------------------------------
// Split fp32 -> (bf16 hi, bf16 lo)
// ---------------------------------------------------------------------------
__global__ __launch_bounds__(256) void split_act(const float* __restrict__ x,
                                                 __nv_bfloat16* __restrict__ hi,
                                                 __nv_bfloat16* __restrict__ lo,
                                                 int n4)
{
    int i = blockIdx.x * 256 + threadIdx.x;
    if (i >= n4) return;
    float4 v = ((const float4*)x)[i];
    __nv_bfloat162 h0 = split_hi2(v.x, v.y), h1 = split_hi2(v.z, v.w);
    ((__nv_bfloat162*)hi)[i * 2 + 0] = h0;
    ((__nv_bfloat162*)hi)[i * 2 + 1] = h1;
    ((__nv_bfloat162*)lo)[i * 2 + 0] = split_lo2(v.x, v.y, h0);
    ((__nv_bfloat162*)lo)[i * 2 + 1] = split_lo2(v.z, v.w, h1);
}

// ---------------------------------------------------------------------------
// Transpose + split weight: W[K,N] fp32 -> WhT/WlT [N,K] bf16
// ---------------------------------------------------------------------------
__global__ __launch_bounds__(256) void split_wT(const float* __restrict__ W,
                                                __nv_bfloat16* __restrict__ hiT,
                                                __nv_bfloat16* __restrict__ loT)
{
    __shared__ float t[32][33];
    int n0 = blockIdx.x * 32, k0 = blockIdx.y * 32;
    int tx = threadIdx.x & 31, ty = threadIdx.x >> 5;
#pragma unroll
    for (int j = 0; j < 4; j++)
        t[ty + 8 * j][tx] = W[(size_t)(k0 + ty + 8 * j) * EE + n0 + tx];
    __syncthreads();
#pragma unroll
    for (int j = 0; j < 4; j++) {
        int n = n0 + ty + 8 * j, k = k0 + tx;
        float v = t[tx][ty + 8 * j];
        __nv_bfloat16 h = __float2bfloat16_rn(v);
        hiT[(size_t)n * EE + k] = h;
        loT[(size_t)n * EE + k] = __float2bfloat16_rn(v - __bfloat162float(h));
    }
}

// ---------------------------------------------------------------------------
// HMMA bf16-split GEMM (2-stage cp.async + ldmatrix). R14: mma reorder —
// term-major over mi so consecutive mmas never target the same accumulator
// (RAW distance 8). z-batched: per-z operand pointers and mode.
// ---------------------------------------------------------------------------
#define GCHUNK 64
#define TILEB 16384
#define STAGEB (4 * TILEB)
#define GEMM_SMEM_BYTES (2 * STAGEB)             // 131072

struct GemmArgs {
    const __nv_bfloat16 *Ah[3], *Al[3], *BhT[3], *BlT[3];
    const float* bias[3];
    float* Cout[3];
    __nv_bfloat16 *Hob[3], *Lob[3];
    int mode[3];
};

__global__ __launch_bounds__(256, 1) void gemm_bf16split(GemmArgs ga)
{
    extern __shared__ char sg[];
    uint32_t sb = smem_u32(sg);
    int z = blockIdx.z;
    const __nv_bfloat16* __restrict__ Ah = ga.Ah[z];
    const __nv_bfloat16* __restrict__ Al = ga.Al[z];
    const __nv_bfloat16* __restrict__ BhT = ga.BhT[z];
    const __nv_bfloat16* __restrict__ BlT = ga.BlT[z];
    const float* __restrict__ bias = ga.bias[z];
    int mode = ga.mode[z];

    int tid = threadIdx.x, wid = tid >> 5, lane = tid & 31;
    int brow = blockIdx.y * 128, bcol = blockIdx.x * 128;
    int m0 = (wid >> 2) * 64, n0 = (wid & 3) * 32;
    int g = lane >> 2, t = lane & 3;
    int j = lane & 7, mh = (lane >> 3) & 1, mc = lane >> 4;

    float c[4][4][4];
#pragma unroll
    for (int mi = 0; mi < 4; mi++)
#pragma unroll
        for (int nj = 0; nj < 4; nj++)
#pragma unroll
            for (int q = 0; q < 4; q++) c[mi][nj][q] = 0.f;

    int lr[4], lkq[4]; uint32_t ldst[4];
#pragma unroll
    for (int i = 0; i < 4; i++) {
        int u = tid + i * 256;
        lr[i] = u >> 3; lkq[i] = u & 7;
        ldst[i] = (uint32_t)(lr[i] * GCHUNK + ((lkq[i] ^ (lr[i] & 7)) * 8)) * 2;
    }

#pragma unroll
    for (int i = 0; i < 4; i++) {
        size_t gadr = (size_t)(brow + lr[i]) * EE + lkq[i] * 8;
        size_t gb = (size_t)(bcol + lr[i]) * EE + lkq[i] * 8;
        CP_ASYNC16(sb + 0 * TILEB + ldst[i], Ah + gadr);
        CP_ASYNC16(sb + 1 * TILEB + ldst[i], Al + gadr);
        CP_ASYNC16(sb + 2 * TILEB + ldst[i], BhT + gb);
        CP_ASYNC16(sb + 3 * TILEB + ldst[i], BlT + gb);
    }
    CP_COMMIT();

    for (int kc = 0; kc < EE / GCHUNK; kc++) {
        uint32_t cur = sb + (uint32_t)(kc & 1) * STAGEB;
        if (kc + 1 < EE / GCHUNK) {
            uint32_t nxt = sb + (uint32_t)((kc + 1) & 1) * STAGEB;
            int k0 = (kc + 1) * GCHUNK;
#pragma unroll
            for (int i = 0; i < 4; i++) {
                size_t gadr = (size_t)(brow + lr[i]) * EE + k0 + lkq[i] * 8;
                size_t gb = (size_t)(bcol + lr[i]) * EE + k0 + lkq[i] * 8;
                CP_ASYNC16(nxt + 0 * TILEB + ldst[i], Ah + gadr);
                CP_ASYNC16(nxt + 1 * TILEB + ldst[i], Al + gadr);
                CP_ASYNC16(nxt + 2 * TILEB + ldst[i], BhT + gb);
                CP_ASYNC16(nxt + 3 * TILEB + ldst[i], BlT + gb);
            }
            CP_COMMIT();
            CP_WAIT(1);
        } else {
            CP_WAIT(0);
        }
        __syncthreads();

#pragma unroll
        for (int ks = 0; ks < GCHUNK / 16; ks++) {
            int kk = ks * 16;
            uint32_t ah[4][4], al[4][4];
#pragma unroll
            for (int mi = 0; mi < 4; mi++) {
                int R = m0 + mi * 16 + mh * 8 + j;
                uint32_t grp = (uint32_t)(((kk >> 3) + mc) ^ (R & 7));
                uint32_t off = (uint32_t)(R * GCHUNK) * 2 + grp * 16;
                ldm4(ah[mi], cur + 0 * TILEB + off);
                ldm4(al[mi], cur + 1 * TILEB + off);
            }
#pragma unroll
            for (int njp = 0; njp < 2; njp++) {
                int Cn = n0 + njp * 16 + mc * 8 + j;
                uint32_t grp = (uint32_t)(((kk >> 3) + mh) ^ (Cn & 7));
                uint32_t off = (uint32_t)(Cn * GCHUNK) * 2 + grp * 16;
                uint32_t bh4[4], bl4[4];
                ldm4(bh4, cur + 2 * TILEB + off);
                ldm4(bl4, cur + 3 * TILEB + off);
                // term-major: per-accumulator order (hh, hl, lh) preserved;
                // consecutive mmas hit distinct accumulators (RAW dist 8)
#pragma unroll
                for (int mi = 0; mi < 4; mi++) {
                    mma16816(c[mi][2 * njp],     ah[mi], bh4);
                    mma16816(c[mi][2 * njp + 1], ah[mi], bh4 + 2);
                }
#pragma unroll
                for (int mi = 0; mi < 4; mi++) {
                    mma16816(c[mi][2 * njp],     ah[mi], bl4);
                    mma16816(c[mi][2 * njp + 1], ah[mi], bl4 + 2);
                }
#pragma unroll
                for (int mi = 0; mi < 4; mi++) {
                    mma16816(c[mi][2 * njp],     al[mi], bh4);
                    mma16816(c[mi][2 * njp + 1], al[mi], bh4 + 2);
                }
            }
        }
        __syncthreads();
    }

#pragma unroll
    for (int mi = 0; mi < 4; mi++)
#pragma unroll
        for (int nj = 0; nj < 4; nj++) {
            int r0 = brow + m0 + mi * 16 + g;
            int r1 = r0 + 8;
            int cc = bcol + n0 + nj * 8 + 2 * t;
            float2 bi = *(const float2*)&bias[cc];
            float2 v0 = make_float2(c[mi][nj][0] + bi.x, c[mi][nj][1] + bi.y);
            float2 v1 = make_float2(c[mi][nj][2] + bi.x, c[mi][nj][3] + bi.y);
            if (mode == 0) {
                float* Cout = ga.Cout[z];
                *(float2*)&Cout[(size_t)r0 * EE + cc] = v0;
                *(float2*)&Cout[(size_t)r1 * EE + cc] = v1;
            } else {
                __nv_bfloat16* Hob = ga.Hob[z];
                __nv_bfloat16* Lob = ga.Lob[z];
                int h = cc >> 6, d = cc & 63;
                int b0 = r0 >> 11, s0 = r0 & 2047;
                int b1 = r1 >> 11, s1 = r1 & 2047;
                __nv_bfloat162 h0 = split_hi2(v0.x, v0.y);
                __nv_bfloat162 l0 = split_lo2(v0.x, v0.y, h0);
                __nv_bfloat162 h1 = split_hi2(v1.x, v1.y);
                __nv_bfloat162 l1 = split_lo2(v1.x, v1.y, h1);
                if (mode == 1) {
                    size_t a0 = (((size_t)(b0 * HH + h)) * SS + s0) * DD + d;
                    size_t a1 = (((size_t)(b1 * HH + h)) * SS + s1) * DD + d;
                    *(__nv_bfloat162*)&Hob[a0] = h0;
                    *(__nv_bfloat162*)&Lob[a0] = l0;
                    *(__nv_bfloat162*)&Hob[a1] = h1;
                    *(__nv_bfloat162*)&Lob[a1] = l1;
                } else {
                    size_t base0 = (((size_t)(b0 * HH + h)) * DD + d) * SS;
                    size_t base1 = (((size_t)(b1 * HH + h)) * DD + d) * SS;
                    Hob[base0 + s0]      = h0.x;  Hob[base0 + SS + s0] = h0.y;
                    Lob[base0 + s0]      = l0.x;  Lob[base0 + SS + s0] = l0.y;
                    Hob[base1 + s1]      = h1.x;  Hob[base1 + SS + s1] = h1.y;
                    Lob[base1 + s1]      = l1.x;  Lob[base1 + SS + s1] = l1.y;
                }
            }
        }
}

// ---------------------------------------------------------------------------
// HMMA attention. R14: two-njp mma round-robin (RAW distance 4) layered on
// the R12 half-tile pipeline (exp interleaved with mma issue).
// ---------------------------------------------------------------------------
#define PQ 72
#define PV 136

struct KVStage {
    __nv_bfloat16 Kh[128 * PQ], Kl[128 * PQ];
    __nv_bfloat16 Vth[64 * PV], Vtl[64 * PV];
};
struct ASmem {
    __nv_bfloat16 Qh[128 * PQ], Ql[128 * PQ];
    KVStage st[2];
};

__global__ __launch_bounds__(256, 1) void attn_mma(float* __restrict__ attn_out,
                                                   int write_attn)
{
    extern __shared__ char raw[];
    ASmem& sm = *reinterpret_cast<ASmem*>(raw);
    uint32_t bQh = smem_u32(sm.Qh), bQl = smem_u32(sm.Ql);
    uint32_t bst[2] = { smem_u32(&sm.st[0]), smem_u32(&sm.st[1]) };
    const uint32_t oKh = 0, oKl = 128 * PQ * 2;
    const uint32_t oVh = 2 * 128 * PQ * 2, oVl = 2 * 128 * PQ * 2 + 64 * PV * 2;

    int tid = threadIdx.x, wid = tid >> 5, lane = tid & 31;
    int g = lane >> 2, t = lane & 3;
    int j = lane & 7, mh = (lane >> 3) & 1, mc = lane >> 4;
    int m0 = wid * 16;

    int rt = blockIdx.x, h = blockIdx.y, b = blockIdx.z;
    int bh = b * HH + h;
    const __nv_bfloat16* Qh = g_PQh + ((size_t)bh * SS + rt * 128) * DD;
    const __nv_bfloat16* Ql = g_PQl + ((size_t)bh * SS + rt * 128) * DD;
    const __nv_bfloat16* Khg = g_PKh + (size_t)bh * SS * DD;
    const __nv_bfloat16* Klg = g_PKl + (size_t)bh * SS * DD;
    const __nv_bfloat16* Vhg = g_PVth + (size_t)bh * DD * SS;
    const __nv_bfloat16* Vlg = g_PVtl + (size_t)bh * DD * SS;

    int kr[4], kc8[4], vr[4], vc[4]; uint32_t kdst[4], vdst[4];
#pragma unroll
    for (int i = 0; i < 4; i++) {
        int u = tid + i * 256;
        kr[i] = u >> 3; kc8[i] = u & 7;
        kdst[i] = (uint32_t)(kr[i] * PQ + kc8[i] * 8) * 2;
        vr[i] = u >> 4; vc[i] = u & 15;
        vdst[i] = (uint32_t)(vr[i] * PV + vc[i] * 8) * 2;
    }

#pragma unroll
    for (int i = 0; i < 4; i++) {
        *(uint4*)&sm.Qh[kr[i] * PQ + kc8[i] * 8] = *(const uint4*)(Qh + kr[i] * DD + kc8[i] * 8);
        *(uint4*)&sm.Ql[kr[i] * PQ + kc8[i] * 8] = *(const uint4*)(Ql + kr[i] * DD + kc8[i] * 8);
    }

#pragma unroll
    for (int i = 0; i < 4; i++) {
        size_t gk = (size_t)kr[i] * DD + kc8[i] * 8;
        size_t gv = (size_t)vr[i] * SS + vc[i] * 8;
        CP_ASYNC16(bst[0] + oKh + kdst[i], Khg + gk);
        CP_ASYNC16(bst[0] + oKl + kdst[i], Klg + gk);
        CP_ASYNC16(bst[0] + oVh + vdst[i], Vhg + gv);
        CP_ASYNC16(bst[0] + oVl + vdst[i], Vlg + gv);
    }
    CP_COMMIT();

    uint32_t qrow = (uint32_t)((m0 + mh * 8 + j) * PQ) * 2 + (uint32_t)mc * 16;
    uint32_t krow = (uint32_t)((mc * 8 + j) * PQ) * 2 + (uint32_t)mh * 16;
    uint32_t vrow = (uint32_t)((mc * 8 + j) * PV) * 2 + (uint32_t)mh * 16;

    float acc[8][4];
#pragma unroll
    for (int nj = 0; nj < 8; nj++)
#pragma unroll
        for (int q = 0; q < 4; q++) acc[nj][q] = 0.f;
    float l0 = 0.f, l1 = 0.f;
    const float sc = 0.125f;

    __syncthreads();

    for (int ct = 0; ct < 16; ct++) {
        uint32_t cur = bst[ct & 1];
        if (ct + 1 < 16) {
            uint32_t nxt = bst[(ct + 1) & 1];
            const __nv_bfloat16* Khn = Khg + (size_t)(ct + 1) * 128 * DD;
            const __nv_bfloat16* Kln = Klg + (size_t)(ct + 1) * 128 * DD;
            const __nv_bfloat16* Vhn = Vhg + (ct + 1) * 128;
            const __nv_bfloat16* Vln = Vlg + (ct + 1) * 128;
#pragma unroll
            for (int i = 0; i < 4; i++) {
                size_t gk = (size_t)kr[i] * DD + kc8[i] * 8;
                size_t gv = (size_t)vr[i] * SS + vc[i] * 8;
                CP_ASYNC16(nxt + oKh + kdst[i], Khn + gk);
                CP_ASYNC16(nxt + oKl + kdst[i], Kln + gk);
                CP_ASYNC16(nxt + oVh + vdst[i], Vhn + gv);
                CP_ASYNC16(nxt + oVl + vdst[i], Vln + gv);
            }
            CP_COMMIT();
            CP_WAIT(1);
        } else {
            CP_WAIT(0);
        }
        __syncthreads();

        float s0[8][4], s1[8][4];
#pragma unroll
        for (int nj = 0; nj < 8; nj++)
#pragma unroll
            for (int q = 0; q < 4; q++) { s0[nj][q] = 0.f; s1[nj][q] = 0.f; }

        uint32_t Ph4[8][4], Pl4[8][4];
        float* abase = attn_out + ((size_t)bh * SS + rt * 128 + m0 + g) * SS
                       + ct * 128 + 2 * t;

        // ---- A: QK h0 (njp 0..3), two-njp round-robin ----
#pragma unroll
        for (int ks = 0; ks < 4; ks++) {
            uint32_t kkb = (uint32_t)(ks * 16) * 2;
            uint32_t aqh[4], aql[4];
            ldm4(aqh, bQh + qrow + kkb);
            ldm4(aql, bQl + qrow + kkb);
#pragma unroll
            for (int np = 0; np < 2; np++) {
                int nA = 2 * np, nB = 2 * np + 1;
                uint32_t khA[4], klA[4], khB[4], klB[4];
                ldm4(khA, cur + oKh + krow + (uint32_t)(nA * 16 * PQ) * 2 + kkb);
                ldm4(klA, cur + oKl + krow + (uint32_t)(nA * 16 * PQ) * 2 + kkb);
                ldm4(khB, cur + oKh + krow + (uint32_t)(nB * 16 * PQ) * 2 + kkb);
                ldm4(klB, cur + oKl + krow + (uint32_t)(nB * 16 * PQ) * 2 + kkb);
                mma16816(s0[2 * nA],     aqh, khA); mma16816(s0[2 * nA + 1], aqh, khA + 2);
                mma16816(s0[2 * nB],     aqh, khB); mma16816(s0[2 * nB + 1], aqh, khB + 2);
                mma16816(s0[2 * nA],     aqh, klA); mma16816(s0[2 * nA + 1], aqh, klA + 2);
                mma16816(s0[2 * nB],     aqh, klB); mma16816(s0[2 * nB + 1], aqh, klB + 2);
                mma16816(s0[2 * nA],     aql, khA); mma16816(s0[2 * nA + 1], aql, khA + 2);
                mma16816(s0[2 * nB],     aql, khB); mma16816(s0[2 * nB + 1], aql, khB + 2);
            }
        }

        // ---- B: QK h1 (njp 4..7) interleaved with exp(s0) ----
#pragma unroll
        for (int ks = 0; ks < 4; ks++) {
            uint32_t kkb = (uint32_t)(ks * 16) * 2;
            uint32_t aqh[4], aql[4];
            ldm4(aqh, bQh + qrow + kkb);
            ldm4(aql, bQl + qrow + kkb);
#pragma unroll
            for (int np = 0; np < 2; np++) {
                int nA = 4 + 2 * np, nB = 4 + 2 * np + 1;
                int sA = 2 * (nA - 4), sB = 2 * (nB - 4);
                uint32_t khA[4], klA[4], khB[4], klB[4];
                ldm4(khA, cur + oKh + krow + (uint32_t)(nA * 16 * PQ) * 2 + kkb);
                ldm4(klA, cur + oKl + krow + (uint32_t)(nA * 16 * PQ) * 2 + kkb);
                ldm4(khB, cur + oKh + krow + (uint32_t)(nB * 16 * PQ) * 2 + kkb);
                ldm4(klB, cur + oKl + krow + (uint32_t)(nB * 16 * PQ) * 2 + kkb);
                mma16816(s1[sA],     aqh, khA); mma16816(s1[sA + 1], aqh, khA + 2);
                mma16816(s1[sB],     aqh, khB); mma16816(s1[sB + 1], aqh, khB + 2);
                mma16816(s1[sA],     aqh, klA); mma16816(s1[sA + 1], aqh, klA + 2);
                mma16816(s1[sB],     aqh, klB); mma16816(s1[sB + 1], aqh, klB + 2);
                mma16816(s1[sA],     aql, khA); mma16816(s1[sA + 1], aql, khA + 2);
                mma16816(s1[sB],     aql, khB); mma16816(s1[sB + 1], aql, khB + 2);
            }
            // exp chunk: h0 nj = 2ks, 2ks+1
#pragma unroll
            for (int u2 = 0; u2 < 2; u2++) {
                int nj = 2 * ks + u2;
                float e0 = __expf(s0[nj][0] * sc);
                float e1 = __expf(s0[nj][1] * sc);
                float e2 = __expf(s0[nj][2] * sc);
                float e3 = __expf(s0[nj][3] * sc);
                l0 += e0 + e1;
                l1 += e2 + e3;
                __nv_bfloat162 h01 = split_hi2(e0, e1);
                __nv_bfloat162 h23 = split_hi2(e2, e3);
                int ksx = nj >> 1, idx = (nj & 1) * 2;
                Ph4[ksx][idx]     = b2u(h01);
                Ph4[ksx][idx + 1] = b2u(h23);
                Pl4[ksx][idx]     = b2u(split_lo2(e0, e1, h01));
                Pl4[ksx][idx + 1] = b2u(split_lo2(e2, e3, h23));
                if (write_attn) {
                    float* ap = abase + nj * 8;
                    *(float2*)ap = make_float2(e0, e1);
                    *(float2*)(ap + 8 * (size_t)SS) = make_float2(e2, e3);
                }
            }
        }

        // ---- C: PV ks 0..3 (P0) interleaved with exp(s1), two-njp RR ----
#pragma unroll
        for (int ks = 0; ks < 4; ks++) {
            uint32_t kkb = (uint32_t)(ks * 16) * 2;
#pragma unroll
            for (int np = 0; np < 2; np++) {
                int nA = 2 * np, nB = 2 * np + 1;
                uint32_t vhA[4], vlA[4], vhB[4], vlB[4];
                ldm4(vhA, cur + oVh + vrow + (uint32_t)(nA * 16 * PV) * 2 + kkb);
                ldm4(vlA, cur + oVl + vrow + (uint32_t)(nA * 16 * PV) * 2 + kkb);
                ldm4(vhB, cur + oVh + vrow + (uint32_t)(nB * 16 * PV) * 2 + kkb);
                ldm4(vlB, cur + oVl + vrow + (uint32_t)(nB * 16 * PV) * 2 + kkb);
                mma16816(acc[2 * nA],     Ph4[ks], vhA); mma16816(acc[2 * nA + 1], Ph4[ks], vhA + 2);
                mma16816(acc[2 * nB],     Ph4[ks], vhB); mma16816(acc[2 * nB + 1], Ph4[ks], vhB + 2);
                mma16816(acc[2 * nA],     Ph4[ks], vlA); mma16816(acc[2 * nA + 1], Ph4[ks], vlA + 2);
                mma16816(acc[2 * nB],     Ph4[ks], vlB); mma16816(acc[2 * nB + 1], Ph4[ks], vlB + 2);
                mma16816(acc[2 * nA],     Pl4[ks], vhA); mma16816(acc[2 * nA + 1], Pl4[ks], vhA + 2);
                mma16816(acc[2 * nB],     Pl4[ks], vhB); mma16816(acc[2 * nB + 1], Pl4[ks], vhB + 2);
            }
            // exp chunk: h1 local nj = 2ks, 2ks+1 -> global +8
#pragma unroll
            for (int u2 = 0; u2 < 2; u2++) {
                int ljn = 2 * ks + u2;
                int nj = ljn + 8;
                float e0 = __expf(s1[ljn][0] * sc);
                float e1 = __expf(s1[ljn][1] * sc);
                float e2 = __expf(s1[ljn][2] * sc);
                float e3 = __expf(s1[ljn][3] * sc);
                l0 += e0 + e1;
                l1 += e2 + e3;
                __nv_bfloat162 h01 = split_hi2(e0, e1);
                __nv_bfloat162 h23 = split_hi2(e2, e3);
                int ksx = nj >> 1, idx = (nj & 1) * 2;
                Ph4[ksx][idx]     = b2u(h01);
                Ph4[ksx][idx + 1] = b2u(h23);
                Pl4[ksx][idx]     = b2u(split_lo2(e0, e1, h01));
                Pl4[ksx][idx + 1] = b2u(split_lo2(e2, e3, h23));
                if (write_attn) {
                    float* ap = abase + nj * 8;
                    *(float2*)ap = make_float2(e0, e1);
                    *(float2*)(ap + 8 * (size_t)SS) = make_float2(e2, e3);
                }
            }
        }

        // ---- D: PV ks 4..7 (P1), two-njp RR ----
#pragma unroll
        for (int ks = 4; ks < 8; ks++) {
            uint32_t kkb = (uint32_t)(ks * 16) * 2;
#pragma unroll
            for (int np = 0; np < 2; np++) {
                int nA = 2 * np, nB = 2 * np + 1;
                uint32_t vhA[4], vlA[4], vhB[4], vlB[4];
                ldm4(vhA, cur + oVh + vrow + (uint32_t)(nA * 16 * PV) * 2 + kkb);
                ldm4(vlA, cur + oVl + vrow + (uint32_t)(nA * 16 * PV) * 2 + kkb);
                ldm4(vhB, cur + oVh + vrow + (uint32_t)(nB * 16 * PV) * 2 + kkb);
                ldm4(vlB, cur + oVl + vrow + (uint32_t)(nB * 16 * PV) * 2 + kkb);
                mma16816(acc[2 * nA],     Ph4[ks], vhA); mma16816(acc[2 * nA + 1], Ph4[ks], vhA + 2);
                mma16816(acc[2 * nB],     Ph4[ks], vhB); mma16816(acc[2 * nB + 1], Ph4[ks], vhB + 2);
                mma16816(acc[2 * nA],     Ph4[ks], vlA); mma16816(acc[2 * nA + 1], Ph4[ks], vlA + 2);
                mma16816(acc[2 * nB],     Ph4[ks], vlB); mma16816(acc[2 * nB + 1], Ph4[ks], vlB + 2);
                mma16816(acc[2 * nA],     Pl4[ks], vhA); mma16816(acc[2 * nA + 1], Pl4[ks], vhA + 2);
                mma16816(acc[2 * nB],     Pl4[ks], vhB); mma16816(acc[2 * nB + 1], Pl4[ks], vhB + 2);
            }
        }
        __syncthreads();
    }

    // ---- epilogue ----
    l0 += __shfl_xor_sync(0xffffffffu, l0, 1);
    l0 += __shfl_xor_sync(0xffffffffu, l0, 2);
    l1 += __shfl_xor_sync(0xffffffffu, l1, 1);
    l1 += __shfl_xor_sync(0xffffffffu, l1, 2);
    float inv0 = 1.0f / l0, inv1 = 1.0f / l1;

    int r0 = rt * 128 + m0 + g;
#pragma unroll
    for (int nj = 0; nj < 8; nj++) {
        int d = nj * 8 + 2 * t;
        float w0x = acc[nj][0] * inv0, w0y = acc[nj][1] * inv0;
        float w1x = acc[nj][2] * inv1, w1y = acc[nj][3] * inv1;
        __nv_bfloat162 h0 = split_hi2(w0x, w0y);
        __nv_bfloat162 h1 = split_hi2(w1x, w1y);
        size_t a0 = ((size_t)b * SS + r0) * EE + h * DD + d;
        size_t a1 = ((size_t)b * SS + r0 + 8) * EE + h * DD + d;
        *(__nv_bfloat162*)&g_wth[a0] = h0;
        *(__nv_bfloat162*)&g_wtl[a0] = split_lo2(w0x, w0y, h0);
        *(__nv_bfloat162*)&g_wth[a1] = h1;
        *(__nv_bfloat162*)&g_wtl[a1] = split_lo2(w1x, w1y, h1);
    }
    if (t == 0) {
        g_l[(size_t)bh * SS + r0] = l0;
        g_l[(size_t)bh * SS + r0 + 8] = l1;
    }
}

// ---------------------------------------------------------------------------
// Normalize attn rows by 1/l (pure bandwidth)
// ---------------------------------------------------------------------------
__global__ __launch_bounds__(256) void attn_norm(float* __restrict__ attn)
{
    int row = blockIdx.x;
    float inv = 1.0f / g_l[row];
    float4* p = (float4*)(attn + (size_t)row * SS);
#pragma unroll
    for (int i = threadIdx.x; i < SS / 4; i += 256) {
        float4 v = p[i];
        v.x *= inv; v.y *= inv; v.z *= inv; v.w *= inv;
        p[i] = v;
    }
}

// ---------------------------------------------------------------------------
extern "C" void kernel_launch(void* const* d_in, const int* in_sizes, int n_in,
                              void* d_out, int out_size)
{
    const float* query = (const float*)d_in[0];
    const float* key_  = (const float*)d_in[1];
    const float* value = (const float*)d_in[2];
    const float* Wq = (const float*)d_in[3];
    const float* bq = (const float*)d_in[4];
    const float* Wk = (const float*)d_in[5];
    const float* bk = (const float*)d_in[6];
    const float* Wv = (const float*)d_in[7];
    const float* bv = (const float*)d_in[8];
    const float* Wo = (const float*)d_in[9];
    const float* bo = (const float*)d_in[10];

    float* out = (float*)d_out;
    long long out1 = (long long)BS * EE;
    long long attn_n = (long long)BB * HH * SS * SS;
    int write_attn = ((long long)out_size >= out1 + attn_n) ? 1 : 0;
    float* attn = out + out1;

    __nv_bfloat16 *qh, *ql, *kh, *kl, *vh, *vl, *wth, *wtl;
    __nv_bfloat16 *WqhT, *WqlT, *WkhT, *WklT, *WvhT, *WvlT, *WohT, *WolT;
    __nv_bfloat16 *PQh, *PQl, *PKh, *PKl, *PVth, *PVtl;
    cudaGetSymbolAddress((void**)&qh, g_qh);   cudaGetSymbolAddress((void**)&ql, g_ql);
    cudaGetSymbolAddress((void**)&kh, g_kh);   cudaGetSymbolAddress((void**)&kl, g_kl);
    cudaGetSymbolAddress((void**)&vh, g_vh);   cudaGetSymbolAddress((void**)&vl, g_vl);
    cudaGetSymbolAddress((void**)&wth, g_wth); cudaGetSymbolAddress((void**)&wtl, g_wtl);
    cudaGetSymbolAddress((void**)&WqhT, g_WqhT); cudaGetSymbolAddress((void**)&WqlT, g_WqlT);
    cudaGetSymbolAddress((void**)&WkhT, g_WkhT); cudaGetSymbolAddress((void**)&WklT, g_WklT);
    cudaGetSymbolAddress((void**)&WvhT, g_WvhT); cudaGetSymbolAddress((void**)&WvlT, g_WvlT);
    cudaGetSymbolAddress((void**)&WohT, g_WohT); cudaGetSymbolAddress((void**)&WolT, g_WolT);
    cudaGetSymbolAddress((void**)&PQh, g_PQh); cudaGetSymbolAddress((void**)&PQl, g_PQl);
    cudaGetSymbolAddress((void**)&PKh, g_PKh); cudaGetSymbolAddress((void**)&PKl, g_PKl);
    cudaGetSymbolAddress((void**)&PVth, g_PVth); cudaGetSymbolAddress((void**)&PVtl, g_PVtl);

    cudaFuncSetAttribute(attn_mma, cudaFuncAttributeMaxDynamicSharedMemorySize,
                         (int)sizeof(ASmem));
    cudaFuncSetAttribute(gemm_bf16split, cudaFuncAttributeMaxDynamicSharedMemorySize,
                         GEMM_SMEM_BYTES);

    int n4 = BS * EE / 4;
    dim3 gsplit((n4 + 255) / 256);
    split_act<<<gsplit, 256>>>(query, qh, ql, n4);
    split_act<<<gsplit, 256>>>(key_,  kh, kl, n4);
    split_act<<<gsplit, 256>>>(value, vh, vl, n4);

    dim3 gwt(EE / 32, EE / 32);
    split_wT<<<gwt, 256>>>(Wq, WqhT, WqlT);
    split_wT<<<gwt, 256>>>(Wk, WkhT, WklT);
    split_wT<<<gwt, 256>>>(Wv, WvhT, WvlT);
    split_wT<<<gwt, 256>>>(Wo, WohT, WolT);

    // Batched QKV projection (grid.z = 3)
    GemmArgs gq = {};
    gq.Ah[0] = qh;  gq.Al[0] = ql;  gq.BhT[0] = WqhT; gq.BlT[0] = WqlT;
    gq.bias[0] = bq; gq.Hob[0] = PQh;  gq.Lob[0] = PQl;  gq.mode[0] = 1;
    gq.Ah[1] = kh;  gq.Al[1] = kl;  gq.BhT[1] = WkhT; gq.BlT[1] = WklT;
    gq.bias[1] = bk; gq.Hob[1] = PKh;  gq.Lob[1] = PKl;  gq.mode[1] = 1;
    gq.Ah[2] = vh;  gq.Al[2] = vl;  gq.BhT[2] = WvhT; gq.BlT[2] = WvlT;
    gq.bias[2] = bv; gq.Hob[2] = PVth; gq.Lob[2] = PVtl; gq.mode[2] = 2;
    dim3 ggemm3(EE / 128, BS / 128, 3);
    gemm_bf16split<<<ggemm3, 256, GEMM_SMEM_BYTES>>>(gq);

    dim3 gattn(SS / 128, HH, BB);
    attn_mma<<<gattn, 256, sizeof(ASmem)>>>(attn, write_attn);

    if (write_attn) {
        attn_norm<<<BHS, 256>>>(attn);
    }

    // Output projection
    GemmArgs go = {};
    go.Ah[0] = wth; go.Al[0] = wtl; go.BhT[0] = WohT; go.BlT[0] = WolT;
    go.bias[0] = bo; go.Cout[0] = out; go.mode[0] = 0;
    dim3 ggemm1(EE / 128, BS / 128, 1);
    gemm_bf16split<<<ggemm1, 256, GEMM_SMEM_BYTES>>>(go);
}

// round 16
// speedup vs baseline: 1.4339x; 1.4339x over previous
#include <cuda_runtime.h>
#include <cuda_bf16.h>
#include <cstdint>

#define BB 2
#define SS 2048
#define EE 1024
#define HH 16
#define DD 64
#define BS (BB*SS)      // 4096
#define BHS (BB*HH*SS)  // 65536

// ---------------------------------------------------------------------------
// Scratch (device globals; no allocation allowed)
// ---------------------------------------------------------------------------
__device__ float g_l[BHS];           // softmax row sums

__device__ __nv_bfloat16 g_qh[BS*EE], g_ql[BS*EE];
__device__ __nv_bfloat16 g_kh[BS*EE], g_kl[BS*EE];
__device__ __nv_bfloat16 g_vh[BS*EE], g_vl[BS*EE];
__device__ __nv_bfloat16 g_wth[BS*EE], g_wtl[BS*EE];
__device__ __nv_bfloat16 g_WqhT[EE*EE], g_WqlT[EE*EE];
__device__ __nv_bfloat16 g_WkhT[EE*EE], g_WklT[EE*EE];
__device__ __nv_bfloat16 g_WvhT[EE*EE], g_WvlT[EE*EE];
__device__ __nv_bfloat16 g_WohT[EE*EE], g_WolT[EE*EE];
__device__ __nv_bfloat16 g_PQh[BHS*DD], g_PQl[BHS*DD];
__device__ __nv_bfloat16 g_PKh[BHS*DD], g_PKl[BHS*DD];
__device__ __nv_bfloat16 g_PVth[BHS*DD], g_PVtl[BHS*DD];

// ---------------------------------------------------------------------------
// PTX helpers
// ---------------------------------------------------------------------------
__device__ __forceinline__ void mma16816(float* c, const uint32_t* a, const uint32_t* b) {
    asm volatile(
        "mma.sync.aligned.m16n8k16.row.col.f32.bf16.bf16.f32 "
        "{%0,%1,%2,%3}, {%4,%5,%6,%7}, {%8,%9}, {%0,%1,%2,%3};"
        : "+f"(c[0]), "+f"(c[1]), "+f"(c[2]), "+f"(c[3])
        : "r"(a[0]), "r"(a[1]), "r"(a[2]), "r"(a[3]), "r"(b[0]), "r"(b[1]));
}

__device__ __forceinline__ void ldm4(uint32_t* r, uint32_t saddr) {
    asm volatile("ldmatrix.sync.aligned.m8n8.x4.shared.b16 {%0,%1,%2,%3}, [%4];"
                 : "=r"(r[0]), "=r"(r[1]), "=r"(r[2]), "=r"(r[3]) : "r"(saddr));
}

__device__ __forceinline__ uint32_t smem_u32(const void* p) {
    uint32_t a;
    asm("{ .reg .u64 t; cvta.to.shared.u64 t, %1; cvt.u32.u64 %0, t; }" : "=r"(a) : "l"(p));
    return a;
}

#define CP_ASYNC16(dst, src) \
    asm volatile("cp.async.cg.shared.global [%0], [%1], 16;" :: "r"(dst), "l"(src))
#define CP_COMMIT() asm volatile("cp.async.commit_group;" ::: "memory")
#define CP_WAIT(n)  asm volatile("cp.async.wait_group %0;" :: "n"(n) : "memory")

__device__ __forceinline__ __nv_bfloat162 split_hi2(float x, float y) {
    return __nv_bfloat162(__float2bfloat16_rn(x), __float2bfloat16_rn(y));
}
__device__ __forceinline__ __nv_bfloat162 split_lo2(float x, float y,
                                                    __nv_bfloat162 h) {
    return __nv_bfloat162(__float2bfloat16_rn(x - __bfloat162float(h.x)),
                          __float2bfloat16_rn(y - __bfloat162float(h.y)));
}
__device__ __forceinline__ uint32_t b2u(__nv_bfloat162 v) {
    return *reinterpret_cast<uint32_t*>(&v);
}

// ---------------------------------------------------------------------------
// Split fp32 -> (bf16 hi, bf16 lo)
// ---------------------------------------------------------------------------
__global__ __launch_bounds__(256) void split_act(const float* __restrict__ x,
                                                 __nv_bfloat16* __restrict__ hi,
                                                 __nv_bfloat16* __restrict__ lo,
                                                 int n4)
{
    int i = blockIdx.x * 256 + threadIdx.x;
    if (i >= n4) return;
    float4 v = ((const float4*)x)[i];
    __nv_bfloat162 h0 = split_hi2(v.x, v.y), h1 = split_hi2(v.z, v.w);
    ((__nv_bfloat162*)hi)[i * 2 + 0] = h0;
    ((__nv_bfloat162*)hi)[i * 2 + 1] = h1;
    ((__nv_bfloat162*)lo)[i * 2 + 0] = split_lo2(v.x, v.y, h0);
    ((__nv_bfloat162*)lo)[i * 2 + 1] = split_lo2(v.z, v.w, h1);
}

// ---------------------------------------------------------------------------
// Transpose + split weight: W[K,N] fp32 -> WhT/WlT [N,K] bf16
// ---------------------------------------------------------------------------
__global__ __launch_bounds__(256) void split_wT(const float* __restrict__ W,
                                                __nv_bfloat16* __restrict__ hiT,
                                                __nv_bfloat16* __restrict__ loT)
{
    __shared__ float t[32][33];
    int n0 = blockIdx.x * 32, k0 = blockIdx.y * 32;
    int tx = threadIdx.x & 31, ty = threadIdx.x >> 5;
#pragma unroll
    for (int j = 0; j < 4; j++)
        t[ty + 8 * j][tx] = W[(size_t)(k0 + ty + 8 * j) * EE + n0 + tx];
    __syncthreads();
#pragma unroll
    for (int j = 0; j < 4; j++) {
        int n = n0 + ty + 8 * j, k = k0 + tx;
        float v = t[tx][ty + 8 * j];
        __nv_bfloat16 h = __float2bfloat16_rn(v);
        hiT[(size_t)n * EE + k] = h;
        loT[(size_t)n * EE + k] = __float2bfloat16_rn(v - __bfloat162float(h));
    }
}

// ---------------------------------------------------------------------------
// HMMA bf16-split GEMM (2-stage cp.async + ldmatrix), R13 mma ordering,
// z-batched operands (the ONLY delta vs the 814us build).
// ---------------------------------------------------------------------------
#define GCHUNK 64
#define TILEB 16384
#define STAGEB (4 * TILEB)
#define GEMM_SMEM_BYTES (2 * STAGEB)             // 131072

struct GemmArgs {
    const __nv_bfloat16 *Ah[3], *Al[3], *BhT[3], *BlT[3];
    const float* bias[3];
    float* Cout[3];
    __nv_bfloat16 *Hob[3], *Lob[3];
    int mode[3];
};

__global__ __launch_bounds__(256, 1) void gemm_bf16split(GemmArgs ga)
{
    extern __shared__ char sg[];
    uint32_t sb = smem_u32(sg);
    int z = blockIdx.z;
    const __nv_bfloat16* __restrict__ Ah = ga.Ah[z];
    const __nv_bfloat16* __restrict__ Al = ga.Al[z];
    const __nv_bfloat16* __restrict__ BhT = ga.BhT[z];
    const __nv_bfloat16* __restrict__ BlT = ga.BlT[z];
    const float* __restrict__ bias = ga.bias[z];
    int mode = ga.mode[z];

    int tid = threadIdx.x, wid = tid >> 5, lane = tid & 31;
    int brow = blockIdx.y * 128, bcol = blockIdx.x * 128;
    int m0 = (wid >> 2) * 64, n0 = (wid & 3) * 32;
    int g = lane >> 2, t = lane & 3;
    int j = lane & 7, mh = (lane >> 3) & 1, mc = lane >> 4;

    float c[4][4][4];
#pragma unroll
    for (int mi = 0; mi < 4; mi++)
#pragma unroll
        for (int nj = 0; nj < 4; nj++)
#pragma unroll
            for (int q = 0; q < 4; q++) c[mi][nj][q] = 0.f;

    int lr[4], lkq[4]; uint32_t ldst[4];
#pragma unroll
    for (int i = 0; i < 4; i++) {
        int u = tid + i * 256;
        lr[i] = u >> 3; lkq[i] = u & 7;
        ldst[i] = (uint32_t)(lr[i] * GCHUNK + ((lkq[i] ^ (lr[i] & 7)) * 8)) * 2;
    }

#pragma unroll
    for (int i = 0; i < 4; i++) {
        size_t ga_ = (size_t)(brow + lr[i]) * EE + lkq[i] * 8;
        size_t gb = (size_t)(bcol + lr[i]) * EE + lkq[i] * 8;
        CP_ASYNC16(sb + 0 * TILEB + ldst[i], Ah + ga_);
        CP_ASYNC16(sb + 1 * TILEB + ldst[i], Al + ga_);
        CP_ASYNC16(sb + 2 * TILEB + ldst[i], BhT + gb);
        CP_ASYNC16(sb + 3 * TILEB + ldst[i], BlT + gb);
    }
    CP_COMMIT();

    for (int kc = 0; kc < EE / GCHUNK; kc++) {
        uint32_t cur = sb + (uint32_t)(kc & 1) * STAGEB;
        if (kc + 1 < EE / GCHUNK) {
            uint32_t nxt = sb + (uint32_t)((kc + 1) & 1) * STAGEB;
            int k0 = (kc + 1) * GCHUNK;
#pragma unroll
            for (int i = 0; i < 4; i++) {
                size_t ga_ = (size_t)(brow + lr[i]) * EE + k0 + lkq[i] * 8;
                size_t gb = (size_t)(bcol + lr[i]) * EE + k0 + lkq[i] * 8;
                CP_ASYNC16(nxt + 0 * TILEB + ldst[i], Ah + ga_);
                CP_ASYNC16(nxt + 1 * TILEB + ldst[i], Al + ga_);
                CP_ASYNC16(nxt + 2 * TILEB + ldst[i], BhT + gb);
                CP_ASYNC16(nxt + 3 * TILEB + ldst[i], BlT + gb);
            }
            CP_COMMIT();
            CP_WAIT(1);
        } else {
            CP_WAIT(0);
        }
        __syncthreads();

#pragma unroll
        for (int ks = 0; ks < GCHUNK / 16; ks++) {
            int kk = ks * 16;
            uint32_t ah[4][4], al[4][4];
#pragma unroll
            for (int mi = 0; mi < 4; mi++) {
                int R = m0 + mi * 16 + mh * 8 + j;
                uint32_t grp = (uint32_t)(((kk >> 3) + mc) ^ (R & 7));
                uint32_t off = (uint32_t)(R * GCHUNK) * 2 + grp * 16;
                ldm4(ah[mi], cur + 0 * TILEB + off);
                ldm4(al[mi], cur + 1 * TILEB + off);
            }
#pragma unroll
            for (int njp = 0; njp < 2; njp++) {
                int Cn = n0 + njp * 16 + mc * 8 + j;
                uint32_t grp = (uint32_t)(((kk >> 3) + mh) ^ (Cn & 7));
                uint32_t off = (uint32_t)(Cn * GCHUNK) * 2 + grp * 16;
                uint32_t bh4[4], bl4[4];
                ldm4(bh4, cur + 2 * TILEB + off);
                ldm4(bl4, cur + 3 * TILEB + off);
#pragma unroll
                for (int mi = 0; mi < 4; mi++) {
                    mma16816(c[mi][2 * njp],     ah[mi], bh4);
                    mma16816(c[mi][2 * njp],     ah[mi], bl4);
                    mma16816(c[mi][2 * njp],     al[mi], bh4);
                    mma16816(c[mi][2 * njp + 1], ah[mi], bh4 + 2);
                    mma16816(c[mi][2 * njp + 1], ah[mi], bl4 + 2);
                    mma16816(c[mi][2 * njp + 1], al[mi], bh4 + 2);
                }
            }
        }
        __syncthreads();
    }

#pragma unroll
    for (int mi = 0; mi < 4; mi++)
#pragma unroll
        for (int nj = 0; nj < 4; nj++) {
            int r0 = brow + m0 + mi * 16 + g;
            int r1 = r0 + 8;
            int cc = bcol + n0 + nj * 8 + 2 * t;
            float2 bi = *(const float2*)&bias[cc];
            float2 v0 = make_float2(c[mi][nj][0] + bi.x, c[mi][nj][1] + bi.y);
            float2 v1 = make_float2(c[mi][nj][2] + bi.x, c[mi][nj][3] + bi.y);
            if (mode == 0) {
                float* Cout = ga.Cout[z];
                *(float2*)&Cout[(size_t)r0 * EE + cc] = v0;
                *(float2*)&Cout[(size_t)r1 * EE + cc] = v1;
            } else {
                __nv_bfloat16* Hob = ga.Hob[z];
                __nv_bfloat16* Lob = ga.Lob[z];
                int h = cc >> 6, d = cc & 63;
                int b0 = r0 >> 11, s0 = r0 & 2047;
                int b1 = r1 >> 11, s1 = r1 & 2047;
                __nv_bfloat162 h0 = split_hi2(v0.x, v0.y);
                __nv_bfloat162 l0 = split_lo2(v0.x, v0.y, h0);
                __nv_bfloat162 h1 = split_hi2(v1.x, v1.y);
                __nv_bfloat162 l1 = split_lo2(v1.x, v1.y, h1);
                if (mode == 1) {
                    size_t a0 = (((size_t)(b0 * HH + h)) * SS + s0) * DD + d;
                    size_t a1 = (((size_t)(b1 * HH + h)) * SS + s1) * DD + d;
                    *(__nv_bfloat162*)&Hob[a0] = h0;
                    *(__nv_bfloat162*)&Lob[a0] = l0;
                    *(__nv_bfloat162*)&Hob[a1] = h1;
                    *(__nv_bfloat162*)&Lob[a1] = l1;
                } else {
                    size_t base0 = (((size_t)(b0 * HH + h)) * DD + d) * SS;
                    size_t base1 = (((size_t)(b1 * HH + h)) * DD + d) * SS;
                    Hob[base0 + s0]      = h0.x;  Hob[base0 + SS + s0] = h0.y;
                    Lob[base0 + s0]      = l0.x;  Lob[base0 + SS + s0] = l0.y;
                    Hob[base1 + s1]      = h1.x;  Hob[base1 + SS + s1] = h1.y;
                    Lob[base1 + s1]      = l1.x;  Lob[base1 + SS + s1] = l1.y;
                }
            }
        }
}

// ---------------------------------------------------------------------------
// HMMA attention — exact R12/13 version (814us): half-tile pipeline with
// exp interleave, grouped-3 mma, single-njp fragment liveness. No RR.
// ---------------------------------------------------------------------------
#define PQ 72
#define PV 136

struct KVStage {
    __nv_bfloat16 Kh[128 * PQ], Kl[128 * PQ];
    __nv_bfloat16 Vth[64 * PV], Vtl[64 * PV];
};
struct ASmem {
    __nv_bfloat16 Qh[128 * PQ], Ql[128 * PQ];
    KVStage st[2];
};

__global__ __launch_bounds__(256, 1) void attn_mma(float* __restrict__ attn_out,
                                                   int write_attn)
{
    extern __shared__ char raw[];
    ASmem& sm = *reinterpret_cast<ASmem*>(raw);
    uint32_t bQh = smem_u32(sm.Qh), bQl = smem_u32(sm.Ql);
    uint32_t bst[2] = { smem_u32(&sm.st[0]), smem_u32(&sm.st[1]) };
    const uint32_t oKh = 0, oKl = 128 * PQ * 2;
    const uint32_t oVh = 2 * 128 * PQ * 2, oVl = 2 * 128 * PQ * 2 + 64 * PV * 2;

    int tid = threadIdx.x, wid = tid >> 5, lane = tid & 31;
    int g = lane >> 2, t = lane & 3;
    int j = lane & 7, mh = (lane >> 3) & 1, mc = lane >> 4;
    int m0 = wid * 16;

    int rt = blockIdx.x, h = blockIdx.y, b = blockIdx.z;
    int bh = b * HH + h;
    const __nv_bfloat16* Qh = g_PQh + ((size_t)bh * SS + rt * 128) * DD;
    const __nv_bfloat16* Ql = g_PQl + ((size_t)bh * SS + rt * 128) * DD;
    const __nv_bfloat16* Khg = g_PKh + (size_t)bh * SS * DD;
    const __nv_bfloat16* Klg = g_PKl + (size_t)bh * SS * DD;
    const __nv_bfloat16* Vhg = g_PVth + (size_t)bh * DD * SS;
    const __nv_bfloat16* Vlg = g_PVtl + (size_t)bh * DD * SS;

    int kr[4], kc8[4], vr[4], vc[4]; uint32_t kdst[4], vdst[4];
#pragma unroll
    for (int i = 0; i < 4; i++) {
        int u = tid + i * 256;
        kr[i] = u >> 3; kc8[i] = u & 7;
        kdst[i] = (uint32_t)(kr[i] * PQ + kc8[i] * 8) * 2;
        vr[i] = u >> 4; vc[i] = u & 15;
        vdst[i] = (uint32_t)(vr[i] * PV + vc[i] * 8) * 2;
    }

#pragma unroll
    for (int i = 0; i < 4; i++) {
        *(uint4*)&sm.Qh[kr[i] * PQ + kc8[i] * 8] = *(const uint4*)(Qh + kr[i] * DD + kc8[i] * 8);
        *(uint4*)&sm.Ql[kr[i] * PQ + kc8[i] * 8] = *(const uint4*)(Ql + kr[i] * DD + kc8[i] * 8);
    }

#pragma unroll
    for (int i = 0; i < 4; i++) {
        size_t gk = (size_t)kr[i] * DD + kc8[i] * 8;
        size_t gv = (size_t)vr[i] * SS + vc[i] * 8;
        CP_ASYNC16(bst[0] + oKh + kdst[i], Khg + gk);
        CP_ASYNC16(bst[0] + oKl + kdst[i], Klg + gk);
        CP_ASYNC16(bst[0] + oVh + vdst[i], Vhg + gv);
        CP_ASYNC16(bst[0] + oVl + vdst[i], Vlg + gv);
    }
    CP_COMMIT();

    uint32_t qrow = (uint32_t)((m0 + mh * 8 + j) * PQ) * 2 + (uint32_t)mc * 16;
    uint32_t krow = (uint32_t)((mc * 8 + j) * PQ) * 2 + (uint32_t)mh * 16;
    uint32_t vrow = (uint32_t)((mc * 8 + j) * PV) * 2 + (uint32_t)mh * 16;

    float acc[8][4];
#pragma unroll
    for (int nj = 0; nj < 8; nj++)
#pragma unroll
        for (int q = 0; q < 4; q++) acc[nj][q] = 0.f;
    float l0 = 0.f, l1 = 0.f;
    const float sc = 0.125f;

    __syncthreads();

    for (int ct = 0; ct < 16; ct++) {
        uint32_t cur = bst[ct & 1];
        if (ct + 1 < 16) {
            uint32_t nxt = bst[(ct + 1) & 1];
            const __nv_bfloat16* Khn = Khg + (size_t)(ct + 1) * 128 * DD;
            const __nv_bfloat16* Kln = Klg + (size_t)(ct + 1) * 128 * DD;
            const __nv_bfloat16* Vhn = Vhg + (ct + 1) * 128;
            const __nv_bfloat16* Vln = Vlg + (ct + 1) * 128;
#pragma unroll
            for (int i = 0; i < 4; i++) {
                size_t gk = (size_t)kr[i] * DD + kc8[i] * 8;
                size_t gv = (size_t)vr[i] * SS + vc[i] * 8;
                CP_ASYNC16(nxt + oKh + kdst[i], Khn + gk);
                CP_ASYNC16(nxt + oKl + kdst[i], Kln + gk);
                CP_ASYNC16(nxt + oVh + vdst[i], Vhn + gv);
                CP_ASYNC16(nxt + oVl + vdst[i], Vln + gv);
            }
            CP_COMMIT();
            CP_WAIT(1);
        } else {
            CP_WAIT(0);
        }
        __syncthreads();

        float s0[8][4], s1[8][4];
#pragma unroll
        for (int nj = 0; nj < 8; nj++)
#pragma unroll
            for (int q = 0; q < 4; q++) { s0[nj][q] = 0.f; s1[nj][q] = 0.f; }

        uint32_t Ph4[8][4], Pl4[8][4];
        float* abase = attn_out + ((size_t)bh * SS + rt * 128 + m0 + g) * SS
                       + ct * 128 + 2 * t;

        // ---- A: QK h0 (cols 0..63) ----
#pragma unroll
        for (int ks = 0; ks < 4; ks++) {
            uint32_t kkb = (uint32_t)(ks * 16) * 2;
            uint32_t aqh[4], aql[4];
            ldm4(aqh, bQh + qrow + kkb);
            ldm4(aql, bQl + qrow + kkb);
#pragma unroll
            for (int njp = 0; njp < 4; njp++) {
                uint32_t ko = krow + (uint32_t)(njp * 16 * PQ) * 2 + kkb;
                uint32_t kh4[4], kl4[4];
                ldm4(kh4, cur + oKh + ko);
                ldm4(kl4, cur + oKl + ko);
                mma16816(s0[2 * njp],     aqh, kh4);
                mma16816(s0[2 * njp],     aqh, kl4);
                mma16816(s0[2 * njp],     aql, kh4);
                mma16816(s0[2 * njp + 1], aqh, kh4 + 2);
                mma16816(s0[2 * njp + 1], aqh, kl4 + 2);
                mma16816(s0[2 * njp + 1], aql, kh4 + 2);
            }
        }

        // ---- B: QK h1 (cols 64..127) interleaved with exp(s0) ----
#pragma unroll
        for (int ks = 0; ks < 4; ks++) {
            uint32_t kkb = (uint32_t)(ks * 16) * 2;
            uint32_t aqh[4], aql[4];
            ldm4(aqh, bQh + qrow + kkb);
            ldm4(aql, bQl + qrow + kkb);
#pragma unroll
            for (int njp = 4; njp < 8; njp++) {
                uint32_t ko = krow + (uint32_t)(njp * 16 * PQ) * 2 + kkb;
                uint32_t kh4[4], kl4[4];
                ldm4(kh4, cur + oKh + ko);
                ldm4(kl4, cur + oKl + ko);
                int sj = 2 * (njp - 4);
                mma16816(s1[sj],     aqh, kh4);
                mma16816(s1[sj],     aqh, kl4);
                mma16816(s1[sj],     aql, kh4);
                mma16816(s1[sj + 1], aqh, kh4 + 2);
                mma16816(s1[sj + 1], aqh, kl4 + 2);
                mma16816(s1[sj + 1], aql, kh4 + 2);
            }
            // exp chunk: h0 nj = 2ks, 2ks+1 (fills P for PV ks)
#pragma unroll
            for (int u2 = 0; u2 < 2; u2++) {
                int nj = 2 * ks + u2;
                float e0 = __expf(s0[nj][0] * sc);
                float e1 = __expf(s0[nj][1] * sc);
                float e2 = __expf(s0[nj][2] * sc);
                float e3 = __expf(s0[nj][3] * sc);
                l0 += e0 + e1;
                l1 += e2 + e3;
                __nv_bfloat162 h01 = split_hi2(e0, e1);
                __nv_bfloat162 h23 = split_hi2(e2, e3);
                int ksx = nj >> 1, idx = (nj & 1) * 2;
                Ph4[ksx][idx]     = b2u(h01);
                Ph4[ksx][idx + 1] = b2u(h23);
                Pl4[ksx][idx]     = b2u(split_lo2(e0, e1, h01));
                Pl4[ksx][idx + 1] = b2u(split_lo2(e2, e3, h23));
                if (write_attn) {
                    float* ap = abase + nj * 8;
                    *(float2*)ap = make_float2(e0, e1);
                    *(float2*)(ap + 8 * (size_t)SS) = make_float2(e2, e3);
                }
            }
        }

        // ---- C: PV ks 0..3 (uses P0) interleaved with exp(s1) ----
#pragma unroll
        for (int ks = 0; ks < 4; ks++) {
            uint32_t kkb = (uint32_t)(ks * 16) * 2;
#pragma unroll
            for (int njp = 0; njp < 4; njp++) {
                uint32_t vo = vrow + (uint32_t)(njp * 16 * PV) * 2 + kkb;
                uint32_t vh4[4], vl4[4];
                ldm4(vh4, cur + oVh + vo);
                ldm4(vl4, cur + oVl + vo);
                mma16816(acc[2 * njp],     Ph4[ks], vh4);
                mma16816(acc[2 * njp],     Ph4[ks], vl4);
                mma16816(acc[2 * njp],     Pl4[ks], vh4);
                mma16816(acc[2 * njp + 1], Ph4[ks], vh4 + 2);
                mma16816(acc[2 * njp + 1], Ph4[ks], vl4 + 2);
                mma16816(acc[2 * njp + 1], Pl4[ks], vh4 + 2);
            }
            // exp chunk: h1 local nj = 2ks, 2ks+1 -> global col grp +8
#pragma unroll
            for (int u2 = 0; u2 < 2; u2++) {
                int ljn = 2 * ks + u2;
                int nj = ljn + 8;
                float e0 = __expf(s1[ljn][0] * sc);
                float e1 = __expf(s1[ljn][1] * sc);
                float e2 = __expf(s1[ljn][2] * sc);
                float e3 = __expf(s1[ljn][3] * sc);
                l0 += e0 + e1;
                l1 += e2 + e3;
                __nv_bfloat162 h01 = split_hi2(e0, e1);
                __nv_bfloat162 h23 = split_hi2(e2, e3);
                int ksx = nj >> 1, idx = (nj & 1) * 2;
                Ph4[ksx][idx]     = b2u(h01);
                Ph4[ksx][idx + 1] = b2u(h23);
                Pl4[ksx][idx]     = b2u(split_lo2(e0, e1, h01));
                Pl4[ksx][idx + 1] = b2u(split_lo2(e2, e3, h23));
                if (write_attn) {
                    float* ap = abase + nj * 8;
                    *(float2*)ap = make_float2(e0, e1);
                    *(float2*)(ap + 8 * (size_t)SS) = make_float2(e2, e3);
                }
            }
        }

        // ---- D: PV ks 4..7 (uses P1) ----
#pragma unroll
        for (int ks = 4; ks < 8; ks++) {
            uint32_t kkb = (uint32_t)(ks * 16) * 2;
#pragma unroll
            for (int njp = 0; njp < 4; njp++) {
                uint32_t vo = vrow + (uint32_t)(njp * 16 * PV) * 2 + kkb;
                uint32_t vh4[4], vl4[4];
                ldm4(vh4, cur + oVh + vo);
                ldm4(vl4, cur + oVl + vo);
                mma16816(acc[2 * njp],     Ph4[ks], vh4);
                mma16816(acc[2 * njp],     Ph4[ks], vl4);
                mma16816(acc[2 * njp],     Pl4[ks], vh4);
                mma16816(acc[2 * njp + 1], Ph4[ks], vh4 + 2);
                mma16816(acc[2 * njp + 1], Ph4[ks], vl4 + 2);
                mma16816(acc[2 * njp + 1], Pl4[ks], vh4 + 2);
            }
        }
        __syncthreads();
    }

    // ---- epilogue ----
    l0 += __shfl_xor_sync(0xffffffffu, l0, 1);
    l0 += __shfl_xor_sync(0xffffffffu, l0, 2);
    l1 += __shfl_xor_sync(0xffffffffu, l1, 1);
    l1 += __shfl_xor_sync(0xffffffffu, l1, 2);
    float inv0 = 1.0f / l0, inv1 = 1.0f / l1;

    int r0 = rt * 128 + m0 + g;
#pragma unroll
    for (int nj = 0; nj < 8; nj++) {
        int d = nj * 8 + 2 * t;
        float w0x = acc[nj][0] * inv0, w0y = acc[nj][1] * inv0;
        float w1x = acc[nj][2] * inv1, w1y = acc[nj][3] * inv1;
        __nv_bfloat162 h0 = split_hi2(w0x, w0y);
        __nv_bfloat162 h1 = split_hi2(w1x, w1y);
        size_t a0 = ((size_t)b * SS + r0) * EE + h * DD + d;
        size_t a1 = ((size_t)b * SS + r0 + 8) * EE + h * DD + d;
        *(__nv_bfloat162*)&g_wth[a0] = h0;
        *(__nv_bfloat162*)&g_wtl[a0] = split_lo2(w0x, w0y, h0);
        *(__nv_bfloat162*)&g_wth[a1] = h1;
        *(__nv_bfloat162*)&g_wtl[a1] = split_lo2(w1x, w1y, h1);
    }
    if (t == 0) {
        g_l[(size_t)bh * SS + r0] = l0;
        g_l[(size_t)bh * SS + r0 + 8] = l1;
    }
}

// ---------------------------------------------------------------------------
// Normalize attn rows by 1/l (pure bandwidth)
// ---------------------------------------------------------------------------
__global__ __launch_bounds__(256) void attn_norm(float* __restrict__ attn)
{
    int row = blockIdx.x;
    float inv = 1.0f / g_l[row];
    float4* p = (float4*)(attn + (size_t)row * SS);
#pragma unroll
    for (int i = threadIdx.x; i < SS / 4; i += 256) {
        float4 v = p[i];
        v.x *= inv; v.y *= inv; v.z *= inv; v.w *= inv;
        p[i] = v;
    }
}

// ---------------------------------------------------------------------------
extern "C" void kernel_launch(void* const* d_in, const int* in_sizes, int n_in,
                              void* d_out, int out_size)
{
    const float* query = (const float*)d_in[0];
    const float* key_  = (const float*)d_in[1];
    const float* value = (const float*)d_in[2];
    const float* Wq = (const float*)d_in[3];
    const float* bq = (const float*)d_in[4];
    const float* Wk = (const float*)d_in[5];
    const float* bk = (const float*)d_in[6];
    const float* Wv = (const float*)d_in[7];
    const float* bv = (const float*)d_in[8];
    const float* Wo = (const float*)d_in[9];
    const float* bo = (const float*)d_in[10];

    float* out = (float*)d_out;
    long long out1 = (long long)BS * EE;
    long long attn_n = (long long)BB * HH * SS * SS;
    int write_attn = ((long long)out_size >= out1 + attn_n) ? 1 : 0;
    float* attn = out + out1;

    __nv_bfloat16 *qh, *ql, *kh, *kl, *vh, *vl, *wth, *wtl;
    __nv_bfloat16 *WqhT, *WqlT, *WkhT, *WklT, *WvhT, *WvlT, *WohT, *WolT;
    __nv_bfloat16 *PQh, *PQl, *PKh, *PKl, *PVth, *PVtl;
    cudaGetSymbolAddress((void**)&qh, g_qh);   cudaGetSymbolAddress((void**)&ql, g_ql);
    cudaGetSymbolAddress((void**)&kh, g_kh);   cudaGetSymbolAddress((void**)&kl, g_kl);
    cudaGetSymbolAddress((void**)&vh, g_vh);   cudaGetSymbolAddress((void**)&vl, g_vl);
    cudaGetSymbolAddress((void**)&wth, g_wth); cudaGetSymbolAddress((void**)&wtl, g_wtl);
    cudaGetSymbolAddress((void**)&WqhT, g_WqhT); cudaGetSymbolAddress((void**)&WqlT, g_WqlT);
    cudaGetSymbolAddress((void**)&WkhT, g_WkhT); cudaGetSymbolAddress((void**)&WklT, g_WklT);
    cudaGetSymbolAddress((void**)&WvhT, g_WvhT); cudaGetSymbolAddress((void**)&WvlT, g_WvlT);
    cudaGetSymbolAddress((void**)&WohT, g_WohT); cudaGetSymbolAddress((void**)&WolT, g_WolT);
    cudaGetSymbolAddress((void**)&PQh, g_PQh); cudaGetSymbolAddress((void**)&PQl, g_PQl);
    cudaGetSymbolAddress((void**)&PKh, g_PKh); cudaGetSymbolAddress((void**)&PKl, g_PKl);
    cudaGetSymbolAddress((void**)&PVth, g_PVth); cudaGetSymbolAddress((void**)&PVtl, g_PVtl);

    cudaFuncSetAttribute(attn_mma, cudaFuncAttributeMaxDynamicSharedMemorySize,
                         (int)sizeof(ASmem));
    cudaFuncSetAttribute(gemm_bf16split, cudaFuncAttributeMaxDynamicSharedMemorySize,
                         GEMM_SMEM_BYTES);

    int n4 = BS * EE / 4;
    dim3 gsplit((n4 + 255) / 256);
    split_act<<<gsplit, 256>>>(query, qh, ql, n4);
    split_act<<<gsplit, 256>>>(key_,  kh, kl, n4);
    split_act<<<gsplit, 256>>>(value, vh, vl, n4);

    dim3 gwt(EE / 32, EE / 32);
    split_wT<<<gwt, 256>>>(Wq, WqhT, WqlT);
    split_wT<<<gwt, 256>>>(Wk, WkhT, WklT);
    split_wT<<<gwt, 256>>>(Wv, WvhT, WvlT);
    split_wT<<<gwt, 256>>>(Wo, WohT, WolT);

    // Batched QKV projection (grid.z = 3)
    GemmArgs gq = {};
    gq.Ah[0] = qh;  gq.Al[0] = ql;  gq.BhT[0] = WqhT; gq.BlT[0] = WqlT;
    gq.bias[0] = bq; gq.Hob[0] = PQh;  gq.Lob[0] = PQl;  gq.mode[0] = 1;
    gq.Ah[1] = kh;  gq.Al[1] = kl;  gq.BhT[1] = WkhT; gq.BlT[1] = WklT;
    gq.bias[1] = bk; gq.Hob[1] = PKh;  gq.Lob[1] = PKl;  gq.mode[1] = 1;
    gq.Ah[2] = vh;  gq.Al[2] = vl;  gq.BhT[2] = WvhT; gq.BlT[2] = WvlT;
    gq.bias[2] = bv; gq.Hob[2] = PVth; gq.Lob[2] = PVtl; gq.mode[2] = 2;
    dim3 ggemm3(EE / 128, BS / 128, 3);
    gemm_bf16split<<<ggemm3, 256, GEMM_SMEM_BYTES>>>(gq);

    dim3 gattn(SS / 128, HH, BB);
    attn_mma<<<gattn, 256, sizeof(ASmem)>>>(attn, write_attn);

    if (write_attn) {
        attn_norm<<<BHS, 256>>>(attn);
    }

    // Output projection
    GemmArgs go = {};
    go.Ah[0] = wth; go.Al[0] = wtl; go.BhT[0] = WohT; go.BlT[0] = WolT;
    go.bias[0] = bo; go.Cout[0] = out; go.mode[0] = 0;
    dim3 ggemm1(EE / 128, BS / 128, 1);
    gemm_bf16split<<<ggemm1, 256, GEMM_SMEM_BYTES>>>(go);
}